// round 12
// baseline (speedup 1.0000x reference)
#include <cuda_runtime.h>
#include <cuda_bf16.h>
#include <cstdint>

#define DIMN 640
#define BATCH 64
#define MSP 100
#define TRI 205120           // 640*641/2
#define LDA 104              // smem row stride (13 groups of 8; 104 % 32 == 8 -> conflict-free LDS.64)
#define LDT 132              // smem row stride for staged output tile
#define SQRT_EPS 0.0031622776601683794f

// -------- scratch: collision-free partial row sums, rewritten fully each launch --------
__device__ float g_part[BATCH * 5 * DIMN];

__device__ __forceinline__ unsigned f2tf32(float f) {
    unsigned u;
    asm("cvt.rna.tf32.f32 %0, %1;" : "=r"(u) : "f"(f));
    return u;
}
__device__ __forceinline__ float asqrt(float x) {
    float r;
    asm("sqrt.approx.f32 %0, %1;" : "=f"(r) : "f"(x));
    return r;
}
__device__ __forceinline__ void mma_tf32(float c[4], const unsigned a[4], const unsigned b[2]) {
    asm volatile(
        "mma.sync.aligned.m16n8k8.row.col.f32.tf32.tf32.f32 "
        "{%0,%1,%2,%3}, {%4,%5,%6,%7}, {%8,%9}, {%0,%1,%2,%3};"
        : "+f"(c[0]), "+f"(c[1]), "+f"(c[2]), "+f"(c[3])
        : "r"(a[0]), "r"(a[1]), "r"(a[2]), "r"(a[3]), "r"(b[0]), "r"(b[1]));
}

// ---------------- Kernel 1: tf32 Gram tiles + fused norms + BDC epilogue ----------------
__global__ void __launch_bounds__(256, 2)
k_bdc(const float* __restrict__ x, const float* __restrict__ tptr, float* __restrict__ out) {
    extern __shared__ float smem[];
    float* As = smem;                 // [128][LDA], k-paired layout
    float* Bs = smem + 128 * LDA;     // [128][LDA]
    float* Ts = smem;                 // staged output tile [128][LDT], reused after MMA
    __shared__ float rssh[128];
    __shared__ float cssh[128];
    __shared__ float dAs[128];        // tf32-consistent squared norms, A rows
    __shared__ float dBs[128];        // same, B rows

    const int tid = threadIdx.x;
    int b = blockIdx.x / 15;
    int p = blockIdx.x % 15;
    int ti = 0;
    while (p >= 5 - ti) { p -= 5 - ti; ti++; }
    int tj = ti + p;
    const bool diag = (ti == tj);

    // load tiles (tf32-converted) into k-paired layout:
    // within each 8-group, element k goes to slot (k&3)*2 + ((k>>2)&1)
    const float* xa = x + (size_t)(b * DIMN + ti * 128) * MSP;
    const float* xb = x + (size_t)(b * DIMN + tj * 128) * MSP;
    for (int idx = tid; idx < 128 * MSP; idx += 256) {
        int r = idx / MSP;
        int m = idx - r * MSP;
        int nm = (m & ~7) + ((m & 3) << 1) + ((m >> 2) & 1);
        As[r * LDA + nm] = __uint_as_float(f2tf32(xa[idx]));
        if (!diag) Bs[r * LDA + nm] = __uint_as_float(f2tf32(xb[idx]));
    }
    // padding zeros: logical k=100..103 sit in odd slots of group 12: 97,99,101,103
    for (int idx = tid; idx < 128 * 4; idx += 256) {
        int r = idx >> 2, c = idx & 3;
        As[r * LDA + 97 + 2 * c] = 0.f;
        if (!diag) Bs[r * LDA + 97 + 2 * c] = 0.f;
    }
    if (tid < 128) rssh[tid] = 0.f;
    else cssh[tid - 128] = 0.f;
    __syncthreads();

    // ---- in-kernel norms from the tf32 smem tiles (permutation-invariant) ----
    if (tid < 128) {
        const float4* rowp = (const float4*)(As + tid * LDA);
        float s = 0.f;
        #pragma unroll
        for (int m = 0; m < 26; m++) {
            float4 v = rowp[m];
            s = fmaf(v.x, v.x, fmaf(v.y, v.y, fmaf(v.z, v.z, fmaf(v.w, v.w, s))));
        }
        dAs[tid] = s;
    } else if (!diag) {
        const float4* rowp = (const float4*)(Bs + (tid - 128) * LDA);
        float s = 0.f;
        #pragma unroll
        for (int m = 0; m < 26; m++) {
            float4 v = rowp[m];
            s = fmaf(v.x, v.x, fmaf(v.y, v.y, fmaf(v.z, v.z, fmaf(v.w, v.w, s))));
        }
        dBs[tid - 128] = s;
    }

    const float* Bse = diag ? As : Bs;
    const float* dBse = diag ? dAs : dBs;

    const int lane = tid & 31;
    const int w = tid >> 5;
    const int wm = (w >> 2) * 64;   // warp m-offset (2 warps in m)
    const int wn = (w & 3) * 32;    // warp n-offset (4 warps in n)
    const int g = lane >> 2;        // 0..7
    const int tg = lane & 3;        // 0..3

    float acc[4][4][4];
    #pragma unroll
    for (int am = 0; am < 4; am++)
        #pragma unroll
        for (int an = 0; an < 4; an++)
            #pragma unroll
            for (int v = 0; v < 4; v++) acc[am][an][v] = 0.f;

    #pragma unroll
    for (int ks = 0; ks < 13; ks++) {
        const int off = ks * 8 + tg * 2;
        unsigned a[4][4], bf[4][2];
        #pragma unroll
        for (int am = 0; am < 4; am++) {
            const float2 pa0 = *(const float2*)(As + (wm + am * 16 + g) * LDA + off);
            const float2 pa1 = *(const float2*)(As + (wm + am * 16 + g + 8) * LDA + off);
            a[am][0] = __float_as_uint(pa0.x);
            a[am][1] = __float_as_uint(pa1.x);
            a[am][2] = __float_as_uint(pa0.y);
            a[am][3] = __float_as_uint(pa1.y);
        }
        #pragma unroll
        for (int an = 0; an < 4; an++) {
            const float2 pb = *(const float2*)(Bse + (wn + an * 8 + g) * LDA + off);
            bf[an][0] = __float_as_uint(pb.x);
            bf[an][1] = __float_as_uint(pb.y);
        }
        #pragma unroll
        for (int am = 0; am < 4; am++)
            #pragma unroll
            for (int an = 0; an < 4; an++) mma_tf32(acc[am][an], a[am], bf[an]);
    }

    __syncthreads();   // norms visible; operand reads done -> Ts may overwrite

    // ---- epilogue: dcov transform, stage into smem tile ----
    const float s = expf(tptr[0]);
    float drow[8], dcol[8];
    #pragma unroll
    for (int am = 0; am < 4; am++) {
        drow[2 * am]     = dAs[wm + am * 16 + g];
        drow[2 * am + 1] = dAs[wm + am * 16 + g + 8];
    }
    #pragma unroll
    for (int an = 0; an < 4; an++) {
        dcol[2 * an]     = dBse[wn + an * 8 + 2 * tg];
        dcol[2 * an + 1] = dBse[wn + an * 8 + 2 * tg + 1];
    }

    float rp[8], cp[8];
    #pragma unroll
    for (int q = 0; q < 8; q++) { rp[q] = 0.f; cp[q] = 0.f; }

    #pragma unroll
    for (int am = 0; am < 4; am++) {
        #pragma unroll
        for (int an = 0; an < 4; an++) {
            #pragma unroll
            for (int v = 0; v < 4; v++) {
                const int hi = v >> 1, lo = v & 1;
                const int r = wm + am * 16 + g + hi * 8;   // local row in tile
                const int c = wn + an * 8 + 2 * tg + lo;   // local col in tile
                float q2 = drow[2 * am + hi] + dcol[2 * an + lo] - 2.f * acc[am][an][v];
                q2 = fmaxf(q2, 0.f);
                float val = asqrt(fmaf(q2, s, 1e-5f));
                if (diag) {
                    if (c == r) val = SQRT_EPS;
                    if (c > r) { rp[2 * am + hi] += val; cp[2 * an + lo] += val; }
                    else if (c == r) rp[2 * am + hi] += val;
                } else {
                    rp[2 * am + hi] += val;
                    cp[2 * an + lo] += val;
                }
                Ts[r * LDT + c] = val;
            }
        }
    }
    __syncthreads();

    // ---- coalesced stores from staged tile ----
    const int ob = b * TRI;
    const int lane128 = tid & 127;
    if (!diag) {
        #pragma unroll 4
        for (int r = tid >> 7; r < 128; r += 2) {
            const int gi = ti * 128 + r;
            const int gj = tj * 128 + lane128;
            const int rowoff = gi * (DIMN - 1) - ((gi * (gi - 1)) >> 1);  // row start minus gi
            out[ob + rowoff + gj] = Ts[r * LDT + lane128];
        }
    } else {
        #pragma unroll 4
        for (int r = tid >> 7; r < 128; r += 2) {
            const int gi = ti * 128 + r;
            const int rowoff = gi * (DIMN - 1) - ((gi * (gi - 1)) >> 1);
            const int c = r + lane128;
            if (c < 128)
                out[ob + rowoff + ti * 128 + c] = Ts[r * LDT + c];
        }
    }

    // ---- row/col sum reductions into smem ----
    #pragma unroll
    for (int q = 0; q < 8; q++) {
        float r = rp[q];
        r += __shfl_xor_sync(0xffffffffu, r, 1);
        r += __shfl_xor_sync(0xffffffffu, r, 2);
        if (tg == 0) atomicAdd(&rssh[wm + (q >> 1) * 16 + g + (q & 1) * 8], r);
    }
    #pragma unroll
    for (int q = 0; q < 8; q++) {
        float c = cp[q];
        c += __shfl_xor_sync(0xffffffffu, c, 4);
        c += __shfl_xor_sync(0xffffffffu, c, 8);
        c += __shfl_xor_sync(0xffffffffu, c, 16);
        if (g == 0) atomicAdd(&cssh[wn + (q >> 1) * 8 + 2 * tg + (q & 1)], c);
    }
    __syncthreads();

    // ---- collision-free partial-sum writes (no global atomics, no pre-zeroing) ----
    if (!diag) {
        if (tid < 128)
            g_part[(b * 5 + tj) * DIMN + ti * 128 + tid] = rssh[tid];
        else
            g_part[(b * 5 + ti) * DIMN + tj * 128 + (tid - 128)] = cssh[tid - 128];
    } else {
        if (tid < 128)
            g_part[(b * 5 + ti) * DIMN + ti * 128 + tid] = rssh[tid] + cssh[tid];
    }
}

// ---------------- Kernel 2: double centering over flat float4s ----------------
__device__ __forceinline__ int row_start(int i) {   // packed-triu start index of row i
    return (i * (2 * DIMN + 1 - i)) >> 1;
}

__global__ void __launch_bounds__(256)
k_center(float* __restrict__ out) {
    __shared__ float rs[DIMN];
    __shared__ float red[8];
    const int b = blockIdx.x >> 6;
    const int blk = blockIdx.x & 63;      // 0..63
    const int tid = threadIdx.x;
    const float inv = 1.f / (float)DIMN;

    const float* gp = &g_part[b * 5 * DIMN];
    for (int i = tid; i < DIMN; i += 256) {
        float s = gp[i] + gp[DIMN + i] + gp[2 * DIMN + i]
                + gp[3 * DIMN + i] + gp[4 * DIMN + i];
        rs[i] = s * inv;
    }
    __syncthreads();

    // fused grand total: sum(rs)/D == grand_sum/D^2
    {
        float s = rs[tid] + rs[tid + 256];
        if (tid < DIMN - 512) s += rs[tid + 512];
        #pragma unroll
        for (int o = 16; o > 0; o >>= 1) s += __shfl_xor_sync(0xffffffffu, s, o);
        if ((tid & 31) == 0) red[tid >> 5] = s;
    }
    __syncthreads();
    const float total = (red[0] + red[1] + red[2] + red[3] +
                         red[4] + red[5] + red[6] + red[7]) * inv;

    float4* ob = (float4*)(out + (size_t)b * TRI);
    const int NQ = TRI / 4;               // 51280 float4 per batch
    for (int v = blk * 256 + tid; v < NQ; v += 64 * 256) {
        const int k = v << 2;
        // analytic row index: i = (1281 - sqrt(1281^2 - 8k)) / 2, then exact fixup
        const int disc = 1281 * 1281 - 8 * k;
        int i0 = (int)((1281.0f - sqrtf((float)disc)) * 0.5f);
        if (i0 > 0 && row_start(i0) > k) i0--;
        if (row_start(i0 + 1) <= k) i0++;
        if (row_start(i0 + 1) <= k) i0++;
        const int j0 = i0 + (k - row_start(i0));

        float4 val = ob[v];
        if (j0 + 3 < DIMN) {             // fast path: whole quad in row i0
            const float a = total - rs[i0];
            val.x = val.x - rs[j0]     + a;
            val.y = val.y - rs[j0 + 1] + a;
            val.z = val.z - rs[j0 + 2] + a;
            val.w = val.w - rs[j0 + 3] + a;
        } else {                          // row-crossing quad: scalar walk
            int ci = i0, cj = j0;
            float* e = (float*)&val;
            #pragma unroll
            for (int q = 0; q < 4; q++) {
                if (cj >= DIMN) { ci++; cj = ci; }
                e[q] = e[q] - rs[cj] - rs[ci] + total;
                cj++;
            }
        }
        ob[v] = val;
    }
}

extern "C" void kernel_launch(void* const* d_in, const int* in_sizes, int n_in,
                              void* d_out, int out_size) {
    const float* x = (const float*)d_in[0];
    const float* t = (const float*)d_in[1];
    float* out = (float*)d_out;

    const int smem = 2 * 128 * LDA * (int)sizeof(float);  // 106,496 B
    cudaFuncSetAttribute(k_bdc, cudaFuncAttributeMaxDynamicSharedMemorySize, smem);

    k_bdc<<<BATCH * 15, 256, smem>>>(x, t, out);
    k_center<<<BATCH * 64, 256>>>(out);
}

// round 13
// speedup vs baseline: 1.1688x; 1.1688x over previous
#include <cuda_runtime.h>
#include <cuda_bf16.h>
#include <cstdint>

#define DIMN 640
#define BATCH 64
#define MSP 100
#define TRI 205120           // 640*641/2
#define LDA 108              // smem row stride for operands (conflict-free scalar frags)
#define LDT 132              // smem row stride for staged output tile
#define SQRT_EPS 0.0031622776601683794f

// -------- scratch: collision-free partial row sums, rewritten fully each launch --------
__device__ float g_part[BATCH * 5 * DIMN];

__device__ __forceinline__ unsigned f2tf32(float f) {
    unsigned u;
    asm("cvt.rna.tf32.f32 %0, %1;" : "=r"(u) : "f"(f));
    return u;
}
__device__ __forceinline__ float4 cvt4(float4 v) {
    float4 o;
    o.x = __uint_as_float(f2tf32(v.x));
    o.y = __uint_as_float(f2tf32(v.y));
    o.z = __uint_as_float(f2tf32(v.z));
    o.w = __uint_as_float(f2tf32(v.w));
    return o;
}
__device__ __forceinline__ float asqrt(float x) {
    float r;
    asm("sqrt.approx.f32 %0, %1;" : "=f"(r) : "f"(x));
    return r;
}
__device__ __forceinline__ void mma_tf32(float c[4], const unsigned a[4], const unsigned b[2]) {
    asm volatile(
        "mma.sync.aligned.m16n8k8.row.col.f32.tf32.tf32.f32 "
        "{%0,%1,%2,%3}, {%4,%5,%6,%7}, {%8,%9}, {%0,%1,%2,%3};"
        : "+f"(c[0]), "+f"(c[1]), "+f"(c[2]), "+f"(c[3])
        : "r"(a[0]), "r"(a[1]), "r"(a[2]), "r"(a[3]), "r"(b[0]), "r"(b[1]));
}

// ---------------- Kernel 1: tf32 Gram tiles + fused norms + BDC epilogue ----------------
__global__ void __launch_bounds__(256, 2)
k_bdc(const float* __restrict__ x, const float* __restrict__ tptr, float* __restrict__ out) {
    extern __shared__ float smem[];
    float* As = smem;                 // [128][LDA]
    float* Bs = smem + 128 * LDA;     // [128][LDA]
    float* Ts = smem;                 // staged output tile [128][LDT], reused after MMA
    __shared__ float rssh[128];
    __shared__ float cssh[128];
    __shared__ float dAs[128];        // tf32-consistent squared norms, A rows
    __shared__ float dBs[128];        // same, B rows

    const int tid = threadIdx.x;
    int b = blockIdx.x / 15;
    int p = blockIdx.x % 15;
    int ti = 0;
    while (p >= 5 - ti) { p -= 5 - ti; ti++; }
    int tj = ti + p;
    const bool diag = (ti == tj);

    // ---- vectorized fill: 25 float4 per row, tf32-converted ----
    const float4* xa4 = (const float4*)(x + (size_t)(b * DIMN + ti * 128) * MSP);
    const float4* xb4 = (const float4*)(x + (size_t)(b * DIMN + tj * 128) * MSP);
    #pragma unroll 4
    for (int idx = tid; idx < 128 * 25; idx += 256) {
        const int r = idx / 25;
        const int m4 = idx - r * 25;
        *(float4*)(As + r * LDA + m4 * 4) = cvt4(xa4[idx]);
        if (!diag) *(float4*)(Bs + r * LDA + m4 * 4) = cvt4(xb4[idx]);
    }
    // padding: slots 100..107 zero (MMA reads through 103; norms read through 99)
    {
        const float4 z = make_float4(0.f, 0.f, 0.f, 0.f);
        if (tid < 128) {
            *(float4*)(As + tid * LDA + 100) = z;
            *(float4*)(As + tid * LDA + 104) = z;
        } else if (!diag) {
            *(float4*)(Bs + (tid - 128) * LDA + 100) = z;
            *(float4*)(Bs + (tid - 128) * LDA + 104) = z;
        }
    }
    if (tid < 128) rssh[tid] = 0.f;
    else cssh[tid - 128] = 0.f;
    __syncthreads();

    // ---- in-kernel norms from the tf32 smem tiles (conflict-free float4 reads) ----
    if (tid < 128) {
        const float4* rowp = (const float4*)(As + tid * LDA);
        float s = 0.f;
        #pragma unroll
        for (int m = 0; m < 25; m++) {
            float4 v = rowp[m];
            s = fmaf(v.x, v.x, fmaf(v.y, v.y, fmaf(v.z, v.z, fmaf(v.w, v.w, s))));
        }
        dAs[tid] = s;
    } else if (!diag) {
        const float4* rowp = (const float4*)(Bs + (tid - 128) * LDA);
        float s = 0.f;
        #pragma unroll
        for (int m = 0; m < 25; m++) {
            float4 v = rowp[m];
            s = fmaf(v.x, v.x, fmaf(v.y, v.y, fmaf(v.z, v.z, fmaf(v.w, v.w, s))));
        }
        dBs[tid - 128] = s;
    }
    // no sync needed before MMA: MMA reads As/Bs (ready); norms sync at the post-MMA barrier.

    const float* Bse = diag ? As : Bs;
    const float* dBse = diag ? dAs : dBs;

    const int lane = tid & 31;
    const int w = tid >> 5;
    const int wm = (w >> 2) * 64;   // warp m-offset (2 warps in m)
    const int wn = (w & 3) * 32;    // warp n-offset (4 warps in n)
    const int g = lane >> 2;        // 0..7
    const int tg = lane & 3;        // 0..3

    float acc[4][4][4];
    #pragma unroll
    for (int am = 0; am < 4; am++)
        #pragma unroll
        for (int an = 0; an < 4; an++)
            #pragma unroll
            for (int v = 0; v < 4; v++) acc[am][an][v] = 0.f;

    #pragma unroll
    for (int ks = 0; ks < 13; ks++) {
        const int k0 = ks * 8;
        unsigned a[4][4], bf[4][2];
        #pragma unroll
        for (int am = 0; am < 4; am++) {
            const float* r0 = &As[(wm + am * 16 + g) * LDA + k0 + tg];
            const float* r1 = &As[(wm + am * 16 + g + 8) * LDA + k0 + tg];
            a[am][0] = __float_as_uint(r0[0]);
            a[am][1] = __float_as_uint(r1[0]);
            a[am][2] = __float_as_uint(r0[4]);
            a[am][3] = __float_as_uint(r1[4]);
        }
        #pragma unroll
        for (int an = 0; an < 4; an++) {
            const float* br = &Bse[(wn + an * 8 + g) * LDA + k0 + tg];
            bf[an][0] = __float_as_uint(br[0]);
            bf[an][1] = __float_as_uint(br[4]);
        }
        #pragma unroll
        for (int am = 0; am < 4; am++)
            #pragma unroll
            for (int an = 0; an < 4; an++) mma_tf32(acc[am][an], a[am], bf[an]);
    }

    __syncthreads();   // norms visible to all; operand reads done -> Ts may overwrite

    // ---- epilogue: dcov transform, stage into smem tile ----
    const float s = expf(tptr[0]);
    float drow[8], dcol[8];
    #pragma unroll
    for (int am = 0; am < 4; am++) {
        drow[2 * am]     = dAs[wm + am * 16 + g];
        drow[2 * am + 1] = dAs[wm + am * 16 + g + 8];
    }
    #pragma unroll
    for (int an = 0; an < 4; an++) {
        dcol[2 * an]     = dBse[wn + an * 8 + 2 * tg];
        dcol[2 * an + 1] = dBse[wn + an * 8 + 2 * tg + 1];
    }

    float rp[8], cp[8];
    #pragma unroll
    for (int q = 0; q < 8; q++) { rp[q] = 0.f; cp[q] = 0.f; }

    #pragma unroll
    for (int am = 0; am < 4; am++) {
        #pragma unroll
        for (int an = 0; an < 4; an++) {
            #pragma unroll
            for (int v = 0; v < 4; v++) {
                const int hi = v >> 1, lo = v & 1;
                const int r = wm + am * 16 + g + hi * 8;   // local row in tile
                const int c = wn + an * 8 + 2 * tg + lo;   // local col in tile
                float q2 = drow[2 * am + hi] + dcol[2 * an + lo] - 2.f * acc[am][an][v];
                q2 = fmaxf(q2, 0.f);
                float val = asqrt(fmaf(q2, s, 1e-5f));
                if (diag) {
                    if (c == r) val = SQRT_EPS;
                    if (c > r) { rp[2 * am + hi] += val; cp[2 * an + lo] += val; }
                    else if (c == r) rp[2 * am + hi] += val;
                } else {
                    rp[2 * am + hi] += val;
                    cp[2 * an + lo] += val;
                }
                Ts[r * LDT + c] = val;
            }
        }
    }
    __syncthreads();

    // ---- coalesced stores from staged tile ----
    const int ob = b * TRI;
    const int lane128 = tid & 127;
    if (!diag) {
        #pragma unroll 4
        for (int r = tid >> 7; r < 128; r += 2) {
            const int gi = ti * 128 + r;
            const int gj = tj * 128 + lane128;
            const int rowoff = gi * (DIMN - 1) - ((gi * (gi - 1)) >> 1);  // row start minus gi
            out[ob + rowoff + gj] = Ts[r * LDT + lane128];
        }
    } else {
        #pragma unroll 4
        for (int r = tid >> 7; r < 128; r += 2) {
            const int gi = ti * 128 + r;
            const int rowoff = gi * (DIMN - 1) - ((gi * (gi - 1)) >> 1);
            const int c = r + lane128;
            if (c < 128)
                out[ob + rowoff + ti * 128 + c] = Ts[r * LDT + c];
        }
    }

    // ---- row/col sum reductions into smem ----
    #pragma unroll
    for (int q = 0; q < 8; q++) {
        float r = rp[q];
        r += __shfl_xor_sync(0xffffffffu, r, 1);
        r += __shfl_xor_sync(0xffffffffu, r, 2);
        if (tg == 0) atomicAdd(&rssh[wm + (q >> 1) * 16 + g + (q & 1) * 8], r);
    }
    #pragma unroll
    for (int q = 0; q < 8; q++) {
        float c = cp[q];
        c += __shfl_xor_sync(0xffffffffu, c, 4);
        c += __shfl_xor_sync(0xffffffffu, c, 8);
        c += __shfl_xor_sync(0xffffffffu, c, 16);
        if (g == 0) atomicAdd(&cssh[wn + (q >> 1) * 8 + 2 * tg + (q & 1)], c);
    }
    __syncthreads();

    // ---- collision-free partial-sum writes (no global atomics, no pre-zeroing) ----
    if (!diag) {
        if (tid < 128)
            g_part[(b * 5 + tj) * DIMN + ti * 128 + tid] = rssh[tid];
        else
            g_part[(b * 5 + ti) * DIMN + tj * 128 + (tid - 128)] = cssh[tid - 128];
    } else {
        if (tid < 128)
            g_part[(b * 5 + ti) * DIMN + ti * 128 + tid] = rssh[tid] + cssh[tid];
    }
}

// ---------------- Kernel 2: double centering over flat float4s ----------------
__device__ __forceinline__ int row_start(int i) {   // packed-triu start index of row i
    return (i * (2 * DIMN + 1 - i)) >> 1;
}

__global__ void __launch_bounds__(256)
k_center(float* __restrict__ out) {
    __shared__ float rs[DIMN];
    __shared__ float red[8];
    const int b = blockIdx.x >> 6;
    const int blk = blockIdx.x & 63;      // 0..63
    const int tid = threadIdx.x;
    const float inv = 1.f / (float)DIMN;

    const float* gp = &g_part[b * 5 * DIMN];
    for (int i = tid; i < DIMN; i += 256) {
        float s = gp[i] + gp[DIMN + i] + gp[2 * DIMN + i]
                + gp[3 * DIMN + i] + gp[4 * DIMN + i];
        rs[i] = s * inv;
    }
    __syncthreads();

    // fused grand total: sum(rs)/D == grand_sum/D^2
    {
        float s = rs[tid] + rs[tid + 256];
        if (tid < DIMN - 512) s += rs[tid + 512];
        #pragma unroll
        for (int o = 16; o > 0; o >>= 1) s += __shfl_xor_sync(0xffffffffu, s, o);
        if ((tid & 31) == 0) red[tid >> 5] = s;
    }
    __syncthreads();
    const float total = (red[0] + red[1] + red[2] + red[3] +
                         red[4] + red[5] + red[6] + red[7]) * inv;

    float4* ob = (float4*)(out + (size_t)b * TRI);
    const int NQ = TRI / 4;               // 51280 float4 per batch
    for (int v = blk * 256 + tid; v < NQ; v += 64 * 256) {
        const int k = v << 2;
        // analytic row index: i = (1281 - sqrt(1281^2 - 8k)) / 2, then exact fixup
        const int disc = 1281 * 1281 - 8 * k;
        int i0 = (int)((1281.0f - sqrtf((float)disc)) * 0.5f);
        if (i0 > 0 && row_start(i0) > k) i0--;
        if (row_start(i0 + 1) <= k) i0++;
        if (row_start(i0 + 1) <= k) i0++;
        const int j0 = i0 + (k - row_start(i0));

        float4 val = ob[v];
        if (j0 + 3 < DIMN) {             // fast path: whole quad in row i0
            const float a = total - rs[i0];
            val.x = val.x - rs[j0]     + a;
            val.y = val.y - rs[j0 + 1] + a;
            val.z = val.z - rs[j0 + 2] + a;
            val.w = val.w - rs[j0 + 3] + a;
        } else {                          // row-crossing quad: scalar walk
            int ci = i0, cj = j0;
            float* e = (float*)&val;
            #pragma unroll
            for (int q = 0; q < 4; q++) {
                if (cj >= DIMN) { ci++; cj = ci; }
                e[q] = e[q] - rs[cj] - rs[ci] + total;
                cj++;
            }
        }
        ob[v] = val;
    }
}

extern "C" void kernel_launch(void* const* d_in, const int* in_sizes, int n_in,
                              void* d_out, int out_size) {
    const float* x = (const float*)d_in[0];
    const float* t = (const float*)d_in[1];
    float* out = (float*)d_out;

    const int smem = 2 * 128 * LDA * (int)sizeof(float);  // 110,592 B
    cudaFuncSetAttribute(k_bdc, cudaFuncAttributeMaxDynamicSharedMemorySize, smem);

    k_bdc<<<BATCH * 15, 256, smem>>>(x, t, out);
    k_center<<<BATCH * 64, 256>>>(out);
}